// round 3
// baseline (speedup 1.0000x reference)
#include <cuda_runtime.h>
#include <cooperative_groups.h>

namespace cg = cooperative_groups;

#define NB 32          // batches
#define NN 512         // rows (cloud a)
#define NM 512         // cols (cloud b)
#define CL 4           // CTAs per cluster (per batch)
#define RPC (NN / CL)  // rows per CTA = 128
#define SROWS 88       // rows of the block kept in shared memory (multiple of 8)
#define GROWS (RPC - SROWS)  // 40 rows kept in global (L2-resident)
#define NT 512
#define NW (NT / 32)   // 16 warps
#define RW (RPC / NW)  // 8 rows per warp
#define SW (SROWS / RW)  // 11 warps whose rows live in smem
#define NITERS 50
#define INV_EPS 20.0f  // 1/0.05

// L2-resident overflow rows of K: [batch][rank][GROWS][NM]  (8 MB total)
__device__ float g_K[NB][CL][GROWS][NM];
__device__ float g_part[NB][CL];

struct SM {
    float Ks[SROWS * NM];   // 88 x 512 fp32 K tile (176 KB)
    float wpart[NW * NM];   // per-warp column partials (32 KB)
    float v[NM];            // scaled col potential
    float b[NM];            // normalized b weights (0 if masked)
    float pr[2][NM];        // double-buffered partial column sums
    float u[RPC];           // scaled row potential (this CTA's rows)
    float a[RPC];           // normalized a weights
    float ax[RPC];
    float ay[RPC];
    float red[NW];
};

__device__ __forceinline__ float block_sum(float val, float* red, int tid) {
#pragma unroll
    for (int o = 16; o; o >>= 1) val += __shfl_xor_sync(0xffffffffu, val, o);
    if ((tid & 31) == 0) red[tid >> 5] = val;
    __syncthreads();
    if (tid < 32) {
        float r = (tid < NW) ? red[tid] : 0.0f;
#pragma unroll
        for (int o = 8; o; o >>= 1) r += __shfl_xor_sync(0xffffffffu, r, o);
        if (tid == 0) red[0] = r;
    }
    __syncthreads();
    float out = red[0];
    __syncthreads();
    return out;
}

__global__ void __cluster_dims__(CL, 1, 1) __launch_bounds__(NT, 1)
sinkhorn_kernel(const float* __restrict__ a_mask, const float* __restrict__ pc_a,
                const float* __restrict__ b_mask, const float* __restrict__ pc_b) {
    extern __shared__ char smem_raw[];
    SM& sm = *reinterpret_cast<SM*>(smem_raw);

    const int b = blockIdx.y;
    const int rank = blockIdx.x;
    const int r0 = rank * RPC;
    const int tid = threadIdx.x;
    const int lane = tid & 31;
    const int w = tid >> 5;

    cg::cluster_group cluster = cg::this_cluster();
    SM* peer[CL];
#pragma unroll
    for (int r = 0; r < CL; r++)
        peer[r] = reinterpret_cast<SM*>(cluster.map_shared_rank(smem_raw, r));

    float* gk = &g_K[b][rank][0][0];

    // ---------------- prologue ----------------
    // thread tid <-> column m (bx,by live in registers for the whole kernel)
    const float bxr = pc_b[(b * NM + tid) * 3 + 0];
    const float byr = pc_b[(b * NM + tid) * 3 + 1];
    const float bpt = b_mask[b * NM + tid] * pc_b[(b * NM + tid) * 3 + 2];
    const float apt_full = a_mask[b * NN + tid] * pc_a[(b * NN + tid) * 3 + 2];
    const float sumb = block_sum(bpt, sm.red, tid);
    const float suma = block_sum(apt_full, sm.red, tid);
    const float vbm = (bpt > 0.0f) ? 1.0f : 0.0f;

    sm.b[tid] = bpt / sumb;      // 0 for masked cols
    sm.v[tid] = 1.0f;            // v_0 = 1 (matches reference logv = 0)
    if (tid < RPC) {
        int n = r0 + tid;
        float apt = a_mask[b * NN + n] * pc_a[(b * NN + n) * 3 + 2];
        sm.a[tid] = apt / suma;  // 0 for masked rows
        sm.ax[tid] = pc_a[(b * NN + n) * 3 + 0];
        sm.ay[tid] = pc_a[(b * NN + n) * 3 + 1];
    }
    __syncthreads();

    // Build K tile: K = exp(-dist/EPS); dist masked to 0 => K = 1 on masked
    // pairs, exactly matching the reference's logK = 0 there.
    {
#pragma unroll 4
        for (int nl = 0; nl < RPC; nl++) {
            float dx = sm.ax[nl] - bxr;
            float dy = sm.ay[nl] - byr;
            float va = (sm.a[nl] > 0.0f) ? 1.0f : 0.0f;
            float d = sqrtf(fmaf(dx, dx, fmaf(dy, dy, 1e-12f))) * va * vbm;
            float K = __expf(-d * INV_EPS);
            if (nl < SROWS) sm.Ks[nl * NM + tid] = K;
            else            gk[(nl - SROWS) * NM + tid] = K;
        }
    }
    __syncthreads();

    // ------------- Sinkhorn iterations (scaled domain, fused passes) -------
    for (int it = 0; it < NITERS; it++) {
        // Fused pass: for each of this warp's 8 rows,
        //   ru   = sum_m K[r,m] * v[m]        (row dot, K held in registers)
        //   u[r] = a[r] / ru
        //   colacc[m] += K[r,m] * u[r]        (reuses the registers)
        {
            float4 vr[4], cacc[4];
            const float4* v4 = reinterpret_cast<const float4*>(sm.v);
#pragma unroll
            for (int k = 0; k < 4; k++) {
                vr[k] = v4[lane + 32 * k];
                cacc[k] = make_float4(0.0f, 0.0f, 0.0f, 0.0f);
            }

#pragma unroll
            for (int j = 0; j < RW; j++) {
                const int row = w * RW + j;
                const float4* kr = (w < SW)
                    ? reinterpret_cast<const float4*>(sm.Ks + row * NM)
                    : reinterpret_cast<const float4*>(gk + (row - SROWS) * NM);
                float4 kv[4];
                float acc0 = 0.0f, acc1 = 0.0f;
#pragma unroll
                for (int k = 0; k < 4; k++) {
                    kv[k] = kr[lane + 32 * k];
                    acc0 = fmaf(kv[k].x, vr[k].x, acc0);
                    acc1 = fmaf(kv[k].y, vr[k].y, acc1);
                    acc0 = fmaf(kv[k].z, vr[k].z, acc0);
                    acc1 = fmaf(kv[k].w, vr[k].w, acc1);
                }
                float ru = acc0 + acc1;
#pragma unroll
                for (int o = 16; o; o >>= 1)
                    ru += __shfl_xor_sync(0xffffffffu, ru, o);
                // xor-butterfly: every lane holds the full sum
                const float ur = __fdividef(sm.a[row], fmaxf(ru, 1e-30f));
                if (lane == 0) sm.u[row] = ur;
#pragma unroll
                for (int k = 0; k < 4; k++) {
                    cacc[k].x = fmaf(kv[k].x, ur, cacc[k].x);
                    cacc[k].y = fmaf(kv[k].y, ur, cacc[k].y);
                    cacc[k].z = fmaf(kv[k].z, ur, cacc[k].z);
                    cacc[k].w = fmaf(kv[k].w, ur, cacc[k].w);
                }
            }
            float4* wp4 = reinterpret_cast<float4*>(sm.wpart + w * NM);
#pragma unroll
            for (int k = 0; k < 4; k++) wp4[lane + 32 * k] = cacc[k];
        }
        __syncthreads();

        // Cross-warp column reduce: pr[m] = sum_w wpart[w][m]
        {
            const int buf = it & 1;
            float pr = 0.0f;
#pragma unroll
            for (int w2 = 0; w2 < NW; w2++) pr += sm.wpart[w2 * NM + tid];
            sm.pr[buf][tid] = pr;
        }
        cluster.sync();

        // Combine partials from all 4 cluster CTAs, update v locally
        {
            const int buf = it & 1;
            float rv = 0.0f;
#pragma unroll
            for (int r = 0; r < CL; r++) rv += peer[r]->pr[buf][tid];
            sm.v[tid] = __fdividef(sm.b[tid], fmaxf(rv, 1e-30f));
        }
        __syncthreads();
    }

    // -------- epilogue: partial sum of dist^2 * (u K v), no sqrt needed ----
    {
        const float vv = sm.v[tid];
        float acc = 0.0f;
#pragma unroll 4
        for (int nl = 0; nl < RPC; nl++) {
            float dx = sm.ax[nl] - bxr;
            float dy = sm.ay[nl] - byr;
            float d2 = fmaf(dx, dx, fmaf(dy, dy, 1e-12f));  // dist^2
            float K = (nl < SROWS) ? sm.Ks[nl * NM + tid]
                                   : gk[(nl - SROWS) * NM + tid];
            acc = fmaf(d2 * sm.u[nl], K, acc);
        }
        acc *= vv;
        float tot = block_sum(acc, sm.red, tid);
        if (tid == 0) g_part[b][rank] = tot;
    }
    cluster.sync();  // no CTA exits while peers may still read its smem
}

__global__ void __launch_bounds__(NT) finalize_kernel(
    const float* __restrict__ a_mask, const float* __restrict__ pc_a,
    const float* __restrict__ b_mask, const float* __restrict__ pc_b,
    float* __restrict__ out) {
    __shared__ float red[NW];
    int b = blockIdx.x;
    int tid = threadIdx.x;
    float sa = a_mask[b * NN + tid] * pc_a[(b * NN + tid) * 3 + 2];
    float sb = b_mask[b * NM + tid] * pc_b[(b * NM + tid) * 3 + 2];
    float e = block_sum(sa - sb, red, tid);
    if (tid == 0) {
        float ae = fabsf(e);
        float hub = (ae <= 1.0f) ? 0.5f * e * e : (ae - 0.5f);
        out[b] = g_part[b][0] + g_part[b][1] + g_part[b][2] + g_part[b][3] + hub;
    }
}

extern "C" void kernel_launch(void* const* d_in, const int* in_sizes, int n_in,
                              void* d_out, int out_size) {
    const float* a_mask = (const float*)d_in[0];
    const float* pc_a   = (const float*)d_in[1];
    const float* b_mask = (const float*)d_in[2];
    const float* pc_b   = (const float*)d_in[3];

    // Unconditional + idempotent (no static guards per harness rules).
    cudaFuncSetAttribute(sinkhorn_kernel,
                         cudaFuncAttributeMaxDynamicSharedMemorySize,
                         (int)sizeof(SM));

    dim3 grid(CL, NB);
    sinkhorn_kernel<<<grid, NT, sizeof(SM)>>>(a_mask, pc_a, b_mask, pc_b);
    finalize_kernel<<<NB, NT>>>(a_mask, pc_a, b_mask, pc_b, (float*)d_out);
}

// round 10
// speedup vs baseline: 1.5863x; 1.5863x over previous
#include <cuda_runtime.h>
#include <cuda_bf16.h>
#include <cooperative_groups.h>

namespace cg = cooperative_groups;

#define NB 32           // batches
#define NN 512          // rows (cloud a)
#define NM 512          // cols (cloud b)
#define CL 4            // CTAs per cluster (per batch)
#define RPC (NN / CL)   // rows per CTA = 128
#define NT 512
#define NW (NT / 32)    // 16 warps
#define RW (RPC / NW)   // 8 rows per warp
#define NITERS 50
#define INV_EPS 20.0f   // 1/0.05
#define RGUARD 1e-35f   // division guard, below any legitimate row/col sum

struct __align__(16) SM {
    unsigned int Ks32[RPC * (NM / 2)];  // 128x512 bf16 K tile, packed pairs (128 KB)
    float wpart[NW * NM];               // per-warp column partials (32 KB)
    float v[NM];
    float b[NM];
    float bx[NM];
    float by[NM];
    float pr[2][NM];                    // double-buffered cluster col partials
    float u[RPC];
    float a[RPC];
    float ax[RPC];
    float ay[RPC];
    float red[NW];
    float part;                         // this CTA's ot partial
};

// bf16 pair unpack. lo: one shift. hi: reuse the RAW word — mantissa bits 0-15
// are sub-ulp garbage (< 0.78% of the hi value, inside the bf16 quantization
// already accepted for K). Zero ALU ops for hi.
__device__ __forceinline__ float bf_lo(unsigned int p) {
    return __uint_as_float(p << 16);
}
__device__ __forceinline__ float bf_hi(unsigned int p) {
    return __uint_as_float(p);
}

__device__ __forceinline__ void dot8(uint4 k, const float* vr, float& a0, float& a1) {
    a0 = fmaf(bf_lo(k.x), vr[0], a0); a1 = fmaf(bf_hi(k.x), vr[1], a1);
    a0 = fmaf(bf_lo(k.y), vr[2], a0); a1 = fmaf(bf_hi(k.y), vr[3], a1);
    a0 = fmaf(bf_lo(k.z), vr[4], a0); a1 = fmaf(bf_hi(k.z), vr[5], a1);
    a0 = fmaf(bf_lo(k.w), vr[6], a0); a1 = fmaf(bf_hi(k.w), vr[7], a1);
}
__device__ __forceinline__ void axpy8(uint4 k, float s, float* c) {
    c[0] = fmaf(bf_lo(k.x), s, c[0]); c[1] = fmaf(bf_hi(k.x), s, c[1]);
    c[2] = fmaf(bf_lo(k.y), s, c[2]); c[3] = fmaf(bf_hi(k.y), s, c[3]);
    c[4] = fmaf(bf_lo(k.z), s, c[4]); c[5] = fmaf(bf_hi(k.z), s, c[5]);
    c[6] = fmaf(bf_lo(k.w), s, c[6]); c[7] = fmaf(bf_hi(k.w), s, c[7]);
}

// load a 512-float smem array into the 16-reg "pass layout":
// reg[8q + e] = arr[q*256 + lane*8 + e]
__device__ __forceinline__ void load_pass16(const float* arr, int lane, float* r) {
    const float4* a4 = reinterpret_cast<const float4*>(arr);
    float4 t0 = a4[2 * lane], t1 = a4[2 * lane + 1];
    float4 t2 = a4[64 + 2 * lane], t3 = a4[64 + 2 * lane + 1];
    r[0] = t0.x; r[1] = t0.y; r[2] = t0.z; r[3] = t0.w;
    r[4] = t1.x; r[5] = t1.y; r[6] = t1.z; r[7] = t1.w;
    r[8] = t2.x; r[9] = t2.y; r[10] = t2.z; r[11] = t2.w;
    r[12] = t3.x; r[13] = t3.y; r[14] = t3.z; r[15] = t3.w;
}

__device__ __forceinline__ float block_sum(float val, float* red, int tid) {
#pragma unroll
    for (int o = 16; o; o >>= 1) val += __shfl_xor_sync(0xffffffffu, val, o);
    if ((tid & 31) == 0) red[tid >> 5] = val;
    __syncthreads();
    if (tid < 32) {
        float r = (tid < NW) ? red[tid] : 0.0f;
#pragma unroll
        for (int o = 8; o; o >>= 1) r += __shfl_xor_sync(0xffffffffu, r, o);
        if (tid == 0) red[0] = r;
    }
    __syncthreads();
    float out = red[0];
    __syncthreads();
    return out;
}

__global__ void __cluster_dims__(CL, 1, 1) __launch_bounds__(NT, 1)
sinkhorn_kernel(const float* __restrict__ a_mask, const float* __restrict__ pc_a,
                const float* __restrict__ b_mask, const float* __restrict__ pc_b,
                float* __restrict__ out) {
    extern __shared__ char smem_raw[];
    SM* sm = reinterpret_cast<SM*>(smem_raw);

    const int b = blockIdx.y;
    const int rank = blockIdx.x;
    const int r0 = rank * RPC;
    const int tid = threadIdx.x;
    const int lane = tid & 31;
    const int w = tid >> 5;

    cg::cluster_group cluster = cg::this_cluster();
    SM* peer[CL];
#pragma unroll
    for (int r = 0; r < CL; r++)
        peer[r] = reinterpret_cast<SM*>(cluster.map_shared_rank(smem_raw, r));

    // ---------------- prologue ----------------
    const float bxr = pc_b[(b * NM + tid) * 3 + 0];
    const float byr = pc_b[(b * NM + tid) * 3 + 1];
    const float bpt = b_mask[b * NM + tid] * pc_b[(b * NM + tid) * 3 + 2];
    const float apt_full = a_mask[b * NN + tid] * pc_a[(b * NN + tid) * 3 + 2];
    const float sumb = block_sum(bpt, sm->red, tid);
    const float suma = block_sum(apt_full, sm->red, tid);
    const float vbm = (bpt > 0.0f) ? 1.0f : 0.0f;

    sm->b[tid] = bpt / sumb;   // 0 for masked cols
    sm->v[tid] = 1.0f;         // v_0 = 1 (matches reference logv = 0)
    sm->bx[tid] = bxr;
    sm->by[tid] = byr;
    if (tid < RPC) {
        int n = r0 + tid;
        float apt = a_mask[b * NN + n] * pc_a[(b * NN + n) * 3 + 2];
        sm->a[tid] = apt / suma;  // 0 for masked rows
        sm->ax[tid] = pc_a[(b * NN + n) * 3 + 0];
        sm->ay[tid] = pc_a[(b * NN + n) * 3 + 1];
    }
    __syncthreads();

    // Build packed bf16 K tile: K = exp(-dist/EPS); masked pairs -> K = 1
    // (matches reference logK = 0 there). thread tid <-> column tid.
    {
#pragma unroll 4
        for (int nl = 0; nl < RPC; nl++) {
            float dx = sm->ax[nl] - bxr;
            float dy = sm->ay[nl] - byr;
            float va = (sm->a[nl] > 0.0f) ? 1.0f : 0.0f;
            float d = sqrtf(fmaf(dx, dx, fmaf(dy, dy, 1e-12f))) * va * vbm;
            float K = __expf(-d * INV_EPS);
            float Ko = __shfl_xor_sync(0xffffffffu, K, 1);
            if ((tid & 1) == 0) {
                __nv_bfloat162 pk = __floats2bfloat162_rn(K, Ko);  // .x=lo(even col)
                sm->Ks32[nl * (NM / 2) + (tid >> 1)] =
                    *reinterpret_cast<unsigned int*>(&pk);
            }
        }
    }
    __syncthreads();

    // ------------- Sinkhorn iterations (scaled domain) -------------
    for (int it = 0; it < NITERS; it++) {
        float vr[16];
        load_pass16(sm->v, lane, vr);
        float cacc[16];
#pragma unroll
        for (int e = 0; e < 16; e++) cacc[e] = 0.0f;

#pragma unroll
        for (int c = 0; c < 2; c++) {  // 2 chunks of 4 rows
            uint4 ka[4], kb[4];
            float p[4];
#pragma unroll
            for (int j = 0; j < 4; j++) {
                const int row = w * RW + c * 4 + j;
                const uint4* kr =
                    reinterpret_cast<const uint4*>(sm->Ks32 + row * (NM / 2));
                ka[j] = kr[lane];
                kb[j] = kr[32 + lane];
                float a0 = 0.0f, a1 = 0.0f;
                dot8(ka[j], vr, a0, a1);
                dot8(kb[j], vr + 8, a0, a1);
                p[j] = a0 + a1;
            }
            // interleaved butterflies: 4 independent chains
#pragma unroll
            for (int o = 16; o; o >>= 1) {
#pragma unroll
                for (int j = 0; j < 4; j++)
                    p[j] += __shfl_xor_sync(0xffffffffu, p[j], o);
            }
            float ur[4];
#pragma unroll
            for (int j = 0; j < 4; j++) {
                const int row = w * RW + c * 4 + j;
                ur[j] = __fdividef(sm->a[row], fmaxf(p[j], RGUARD));
                if (lane == 0) sm->u[row] = ur[j];
            }
#pragma unroll
            for (int j = 0; j < 4; j++) {
                axpy8(ka[j], ur[j], cacc);
                axpy8(kb[j], ur[j], cacc + 8);
            }
        }

        // dump per-warp column partials (pass layout -> linear)
        {
            float4* wp = reinterpret_cast<float4*>(sm->wpart + w * NM);
            wp[2 * lane] = make_float4(cacc[0], cacc[1], cacc[2], cacc[3]);
            wp[2 * lane + 1] = make_float4(cacc[4], cacc[5], cacc[6], cacc[7]);
            wp[64 + 2 * lane] = make_float4(cacc[8], cacc[9], cacc[10], cacc[11]);
            wp[64 + 2 * lane + 1] = make_float4(cacc[12], cacc[13], cacc[14], cacc[15]);
        }
        __syncthreads();

        // cross-warp column reduce: thread tid <-> column tid
        {
            float prv = 0.0f;
#pragma unroll
            for (int w2 = 0; w2 < NW; w2++) prv += sm->wpart[w2 * NM + tid];
            sm->pr[it & 1][tid] = prv;
        }
        cluster.sync();

        // combine the 4 cluster partials, update v
        {
            float rv = 0.0f;
#pragma unroll
            for (int r = 0; r < CL; r++) rv += peer[r]->pr[it & 1][tid];
            sm->v[tid] = __fdividef(sm->b[tid], fmaxf(rv, RGUARD));
        }
        __syncthreads();
    }

    // -------- epilogue: ot partial = sum d^2 * u K v over own rows --------
    {
        float vrE[16], bxp[16], byp[16], eacc[16];
        load_pass16(sm->v, lane, vrE);
        load_pass16(sm->bx, lane, bxp);
        load_pass16(sm->by, lane, byp);
#pragma unroll
        for (int e = 0; e < 16; e++) eacc[e] = 0.0f;

#pragma unroll
        for (int j = 0; j < RW; j++) {
            const int row = w * RW + j;
            const uint4* kr =
                reinterpret_cast<const uint4*>(sm->Ks32 + row * (NM / 2));
            uint4 ka = kr[lane], kb = kr[32 + lane];
            const float axr = sm->ax[row], ayr = sm->ay[row], ur = sm->u[row];
            float kf[16];
            kf[0] = bf_lo(ka.x); kf[1] = bf_hi(ka.x);
            kf[2] = bf_lo(ka.y); kf[3] = bf_hi(ka.y);
            kf[4] = bf_lo(ka.z); kf[5] = bf_hi(ka.z);
            kf[6] = bf_lo(ka.w); kf[7] = bf_hi(ka.w);
            kf[8] = bf_lo(kb.x); kf[9] = bf_hi(kb.x);
            kf[10] = bf_lo(kb.y); kf[11] = bf_hi(kb.y);
            kf[12] = bf_lo(kb.z); kf[13] = bf_hi(kb.z);
            kf[14] = bf_lo(kb.w); kf[15] = bf_hi(kb.w);
#pragma unroll
            for (int e = 0; e < 16; e++) {
                float dx = axr - bxp[e];
                float dy = ayr - byp[e];
                float d2 = fmaf(dx, dx, fmaf(dy, dy, 1e-12f));
                eacc[e] = fmaf(d2 * ur, kf[e], eacc[e]);
            }
        }
        float s = 0.0f;
#pragma unroll
        for (int e = 0; e < 16; e++) s = fmaf(eacc[e], vrE[e], s);
        float tot = block_sum(s, sm->red, tid);
        if (tid == 0) sm->part = tot;
    }
    cluster.sync();

    // rank 0 finalizes: sum cluster partials + huber term, write out[b]
    if (rank == 0 && tid == 0) {
        float ot = 0.0f;
#pragma unroll
        for (int r = 0; r < CL; r++) ot += peer[r]->part;
        float e = suma - sumb;
        float ae = fabsf(e);
        float hub = (ae <= 1.0f) ? 0.5f * e * e : (ae - 0.5f);
        out[b] = ot + hub;
    }
    cluster.sync();  // peers keep smem alive until rank 0 has read
}

extern "C" void kernel_launch(void* const* d_in, const int* in_sizes, int n_in,
                              void* d_out, int out_size) {
    const float* a_mask = (const float*)d_in[0];
    const float* pc_a   = (const float*)d_in[1];
    const float* b_mask = (const float*)d_in[2];
    const float* pc_b   = (const float*)d_in[3];

    cudaFuncSetAttribute(sinkhorn_kernel,
                         cudaFuncAttributeMaxDynamicSharedMemorySize,
                         (int)sizeof(SM));

    dim3 grid(CL, NB);
    sinkhorn_kernel<<<grid, NT, sizeof(SM)>>>(a_mask, pc_a, b_mask, pc_b,
                                              (float*)d_out);
}